// round 1
// baseline (speedup 1.0000x reference)
#include <cuda_runtime.h>

#define EPSV 1e-5f
#define BGR 4096
#define NCLS 7

// ---------------- device-global folded weights & scratch ----------------
__device__ float d_w1[32], d_b1[32];
__device__ float d_W2[32*64],   d_B2[64];
__device__ float d_W3[64*64],   d_B3[64];
__device__ float d_W4[64*64],   d_B4[64];
__device__ float d_W5T[128*64], d_B5[128];   // W5T[k][m] = a_cbn1[m]*c2a_w[m][k]
__device__ float d_W6[128*128], d_B6[128];
__device__ float d_F1[128*64],  d_FB1[64];
__device__ float d_F2[64*32],   d_FB2[32];
__device__ float d_F3[32*NCLS], d_FB3[NCLS];
__device__ float d_g0[128];                  // g-hat for empty segments
__device__ float d_sums[BGR*128];
__device__ float d_cnts[BGR];

__device__ __forceinline__ float bn_a(const float* bn, int c, int i) {
    return bn[0*c+i] * rsqrtf(bn[3*c+i] + EPSV);
}
__device__ __forceinline__ float bn_c(const float* bn, int c, int i, float a) {
    return bn[1*c+i] - bn[2*c+i]*a;
}

// ---------------- prep: fold BNs into linear layers ----------------
__global__ void prep_kernel(
    const float* w1, const float* b1, const float* bn1,
    const float* w2, const float* b2, const float* bn2,
    const float* c1aw, const float* c1ab,
    const float* c1bw, const float* c1bb, const float* cbn1,
    const float* c2aw, const float* c2ab,
    const float* c2bw, const float* c2bb, const float* cbn2,
    const float* f1w, const float* f1b, const float* fbn1,
    const float* f2w, const float* f2b, const float* fbn2,
    const float* f3w, const float* f3b)
{
    int t = threadIdx.x;  // 256 threads
    for (int i=t;i<32;i+=256){ d_w1[i]=w1[i]; d_b1[i]=b1[i]; }

    for (int i=t;i<32*64;i+=256){ int k=i>>6; d_W2[i]=bn_a(bn1,32,k)*w2[i]; }
    for (int j=t;j<64;j+=256){ float s=b2[j];
        for(int k=0;k<32;k++){float a=bn_a(bn1,32,k); s+=bn_c(bn1,32,k,a)*w2[k*64+j];}
        d_B2[j]=s; }

    for (int i=t;i<64*64;i+=256){ int k=i>>6; d_W3[i]=bn_a(bn2,64,k)*c1aw[i]; }
    for (int j=t;j<64;j+=256){ float s=c1ab[j];
        for(int k=0;k<64;k++){float a=bn_a(bn2,64,k); s+=bn_c(bn2,64,k,a)*c1aw[k*64+j];}
        d_B3[j]=s; }

    for (int i=t;i<64*64;i+=256) d_W4[i]=c1bw[i];
    for (int j=t;j<64;j+=256)    d_B4[j]=c1bb[j];

    for (int i=t;i<128*64;i+=256){ int k=i>>6, m=i&63; d_W5T[i]=bn_a(cbn1,64,m)*c2aw[m*128+k]; }
    for (int k=t;k<128;k+=256){ float s=c2ab[k];
        for(int m=0;m<64;m++){float a=bn_a(cbn1,64,m); s+=bn_c(cbn1,64,m,a)*c2aw[m*128+k];}
        d_B5[k]=s; }

    for (int i=t;i<128*128;i+=256) d_W6[i]=c2bw[i];
    for (int j=t;j<128;j+=256)     d_B6[j]=c2bb[j];

    for (int i=t;i<128*64;i+=256){ int k=i>>6; d_F1[i]=bn_a(cbn2,128,k)*f1w[i]; }
    for (int j=t;j<64;j+=256){ float s=f1b[j];
        for(int k=0;k<128;k++){float a=bn_a(cbn2,128,k); s+=bn_c(cbn2,128,k,a)*f1w[k*64+j];}
        d_FB1[j]=s; }
    for (int k=t;k<128;k+=256){ float a=bn_a(cbn2,128,k); d_g0[k]=-bn_c(cbn2,128,k,a)/a; }

    for (int i=t;i<64*32;i+=256){ int k=i>>5; d_F2[i]=bn_a(fbn1,64,k)*f2w[i]; }
    for (int j=t;j<32;j+=256){ float s=f2b[j];
        for(int k=0;k<64;k++){float a=bn_a(fbn1,64,k); s+=bn_c(fbn1,64,k,a)*f2w[k*32+j];}
        d_FB2[j]=s; }

    for (int i=t;i<32*NCLS;i+=256){ int k=i/NCLS; d_F3[i]=bn_a(fbn2,32,k)*f3w[i]; }
    for (int j=t;j<NCLS;j+=256){ float s=f3b[j];
        for(int k=0;k<32;k++){float a=bn_a(fbn2,32,k); s+=bn_c(fbn2,32,k,a)*f3w[k*NCLS+j];}
        d_FB3[j]=s; }
}

__global__ void zero_kernel() {
    int i = blockIdx.x*blockDim.x + threadIdx.x;
    if (i < BGR*128) d_sums[i] = 0.f;
    if (i < BGR)     d_cnts[i] = 0.f;
}

// ---------------- node kernel ----------------
// shared layout (floats)
#define S_W1   0
#define S_B1   32
#define S_W2   64
#define S_B2   2112
#define S_W3   2176
#define S_B3   6272
#define S_W4   6336
#define S_B4   10432
#define S_W5T  10496
#define S_B5   18688
#define S_W6   18816
#define S_B6   35200
#define S_ACT  35328
#define ACT_STRIDE 68
#define NODE_SMEM_FLOATS (S_ACT + 256*ACT_STRIDE)   // 52736
#define NODE_SMEM_BYTES  (NODE_SMEM_FLOATS*4)       // 210944

__device__ __forceinline__ void cp_s(float* dst, const float* src, int n, int t){
    for (int i=t;i<n;i+=256) dst[i]=src[i];
}

// dense: K=4*K4 inputs (read from padded act scratch), 64 outputs into acc
template<int K4>
__device__ __forceinline__ void dense64(const float* act, const float* W, const float* B, float* acc)
{
    const float4* Bv=(const float4*)B;
    #pragma unroll
    for (int j4=0;j4<16;j4++){ float4 v=Bv[j4];
        acc[4*j4]=v.x; acc[4*j4+1]=v.y; acc[4*j4+2]=v.z; acc[4*j4+3]=v.w; }
    #pragma unroll 1
    for (int k4=0;k4<K4;k4++){
        float4 h=((const float4*)act)[k4];
        #pragma unroll
        for (int kk=0;kk<4;kk++){
            float hk = (kk==0)?h.x:(kk==1)?h.y:(kk==2)?h.z:h.w;
            const float4* Wr=(const float4*)(W + (k4*4+kk)*64);
            #pragma unroll
            for (int j4=0;j4<16;j4++){
                float4 w=Wr[j4];
                acc[4*j4]  =fmaf(hk,w.x,acc[4*j4]);
                acc[4*j4+1]=fmaf(hk,w.y,acc[4*j4+1]);
                acc[4*j4+2]=fmaf(hk,w.z,acc[4*j4+2]);
                acc[4*j4+3]=fmaf(hk,w.w,acc[4*j4+3]);
            }
        }
    }
}

__global__ void __launch_bounds__(256,1)
node_kernel(const float* __restrict__ x, const int* __restrict__ batch, int n)
{
    extern __shared__ float sm[];
    int t = threadIdx.x;
    cp_s(sm+S_W1, d_w1, 32, t);   cp_s(sm+S_B1, d_b1, 32, t);
    cp_s(sm+S_W2, d_W2, 32*64,t); cp_s(sm+S_B2, d_B2, 64, t);
    cp_s(sm+S_W3, d_W3, 64*64,t); cp_s(sm+S_B3, d_B3, 64, t);
    cp_s(sm+S_W4, d_W4, 64*64,t); cp_s(sm+S_B4, d_B4, 64, t);
    cp_s(sm+S_W5T,d_W5T,128*64,t);cp_s(sm+S_B5, d_B5, 128,t);
    cp_s(sm+S_W6, d_W6, 128*128,t);cp_s(sm+S_B6,d_B6, 128,t);
    __syncthreads();

    int e = blockIdx.x*256 + t;
    bool valid = e < n;
    float xv = valid ? x[e] : 0.f;
    int b = valid ? batch[e] : 0;
    float* act = sm + S_ACT + t*ACT_STRIDE;

    // layer1: 1 -> 32 (raw w1/b1; bn1 folded into W2/B2)
    {
        const float* w1s=sm+S_W1; const float* b1s=sm+S_B1;
        #pragma unroll
        for (int j=0;j<32;j++) act[j] = fmaxf(fmaf(xv, w1s[j], b1s[j]), 0.f);
    }
    float acc[64];
    // layer2: 32 -> 64
    dense64<8>(act, sm+S_W2, sm+S_B2, acc);
    #pragma unroll
    for (int j=0;j<64;j++) act[j] = fmaxf(acc[j],0.f);
    // layer3: 64 -> 64
    dense64<16>(act, sm+S_W3, sm+S_B3, acc);
    #pragma unroll
    for (int j=0;j<64;j++) act[j] = fmaxf(acc[j],0.f);
    // layer4: 64 -> 64 (keep result in regs)
    dense64<16>(act, sm+S_W4, sm+S_B4, acc);
    float y4[64];
    #pragma unroll
    for (int j=0;j<64;j++) y4[j] = fmaxf(acc[j],0.f);

    // fused layer5 (64->128) + layer6 (128->128)
    float a6[128];
    {
        const float4* Bv=(const float4*)(sm+S_B6);
        #pragma unroll
        for (int j4=0;j4<32;j4++){ float4 v=Bv[j4];
            a6[4*j4]=v.x; a6[4*j4+1]=v.y; a6[4*j4+2]=v.z; a6[4*j4+3]=v.w; }
    }
    #pragma unroll 1
    for (int k=0;k<128;k++){
        const float4* W5r=(const float4*)(sm+S_W5T + k*64);
        float s0=0.f,s1=0.f,s2=0.f,s3=0.f;
        #pragma unroll
        for (int m4=0;m4<16;m4++){
            float4 w=W5r[m4];
            s0=fmaf(y4[4*m4  ],w.x,s0);
            s1=fmaf(y4[4*m4+1],w.y,s1);
            s2=fmaf(y4[4*m4+2],w.z,s2);
            s3=fmaf(y4[4*m4+3],w.w,s3);
        }
        float y5k = fmaxf((s0+s1)+(s2+s3) + sm[S_B5+k], 0.f);
        const float4* W6r=(const float4*)(sm+S_W6 + k*128);
        #pragma unroll
        for (int j4=0;j4<32;j4++){
            float4 w=W6r[j4];
            a6[4*j4]  =fmaf(y5k,w.x,a6[4*j4]);
            a6[4*j4+1]=fmaf(y5k,w.y,a6[4*j4+1]);
            a6[4*j4+2]=fmaf(y5k,w.z,a6[4*j4+2]);
            a6[4*j4+3]=fmaf(y5k,w.w,a6[4*j4+3]);
        }
    }
    #pragma unroll
    for (int j=0;j<128;j++) a6[j] = valid ? fmaxf(a6[j],0.f) : 0.f;

    // ---- segment accumulation (batch is sorted) ----
    const unsigned FULL = 0xffffffffu;
    int lane = t & 31;
    bool allv = __all_sync(FULL, valid);
    int b0 = __shfl_sync(FULL, b, 0);
    bool uni = allv && __all_sync(FULL, b==b0);
    if (uni) {
        float* dst = d_sums + (size_t)b*128;
        #pragma unroll
        for (int j=0;j<128;j++){
            float v = a6[j];
            v += __shfl_xor_sync(FULL,v,16);
            v += __shfl_xor_sync(FULL,v, 8);
            v += __shfl_xor_sync(FULL,v, 4);
            v += __shfl_xor_sync(FULL,v, 2);
            v += __shfl_xor_sync(FULL,v, 1);
            if (lane == (j&31)) atomicAdd(dst+j, v);
        }
        if (lane==0) atomicAdd(&d_cnts[b], 32.f);
    } else if (valid) {
        float* dst = d_sums + (size_t)b*128;
        #pragma unroll 4
        for (int j=0;j<128;j++) atomicAdd(dst+j, a6[j]);
        atomicAdd(&d_cnts[b], 1.f);
    }
}

// ---------------- graph-level MLP ----------------
#define G_F1   0
#define G_FB1  8192
#define G_F2   8256
#define G_FB2  10304
#define G_F3   10336
#define G_FB3  10560
#define G_G0   10568
#define G_ACT  10696
#define GRAPH_SMEM_FLOATS (G_ACT + 256*ACT_STRIDE)  // 28104
#define GRAPH_SMEM_BYTES  (GRAPH_SMEM_FLOATS*4)     // 112416

__global__ void __launch_bounds__(256,1)
graph_kernel(float* __restrict__ out)
{
    extern __shared__ float sm[];
    int t = threadIdx.x;
    cp_s(sm+G_F1, d_F1, 128*64, t);  cp_s(sm+G_FB1, d_FB1, 64, t);
    cp_s(sm+G_F2, d_F2, 64*32, t);   cp_s(sm+G_FB2, d_FB2, 32, t);
    cp_s(sm+G_F3, d_F3, 32*NCLS, t);
    for (int i=t;i<NCLS;i+=256) sm[G_FB3+i]=d_FB3[i];
    cp_s(sm+G_G0, d_g0, 128, t);
    __syncthreads();

    int row = blockIdx.x*256 + t;
    if (row >= BGR) return;

    float cnt = d_cnts[row];
    bool nz = cnt > 0.5f;
    float inv = nz ? 1.f/cnt : 0.f;
    const float* srow = d_sums + (size_t)row*128;

    float z1[64];
    {
        const float4* Bv=(const float4*)(sm+G_FB1);
        #pragma unroll
        for (int j4=0;j4<16;j4++){ float4 v=Bv[j4];
            z1[4*j4]=v.x; z1[4*j4+1]=v.y; z1[4*j4+2]=v.z; z1[4*j4+3]=v.w; }
    }
    #pragma unroll 1
    for (int k=0;k<128;k++){
        float gk = nz ? __ldg(srow+k)*inv : sm[G_G0+k];
        const float4* Wr=(const float4*)(sm+G_F1 + k*64);
        #pragma unroll
        for (int j4=0;j4<16;j4++){
            float4 w=Wr[j4];
            z1[4*j4]  =fmaf(gk,w.x,z1[4*j4]);
            z1[4*j4+1]=fmaf(gk,w.y,z1[4*j4+1]);
            z1[4*j4+2]=fmaf(gk,w.z,z1[4*j4+2]);
            z1[4*j4+3]=fmaf(gk,w.w,z1[4*j4+3]);
        }
    }
    float* act = sm + G_ACT + t*ACT_STRIDE;
    #pragma unroll
    for (int j=0;j<64;j++) act[j] = fmaxf(z1[j],0.f);

    float z2[32];
    {
        const float4* Bv=(const float4*)(sm+G_FB2);
        #pragma unroll
        for (int j4=0;j4<8;j4++){ float4 v=Bv[j4];
            z2[4*j4]=v.x; z2[4*j4+1]=v.y; z2[4*j4+2]=v.z; z2[4*j4+3]=v.w; }
    }
    #pragma unroll 1
    for (int k4=0;k4<16;k4++){
        float4 h=((const float4*)act)[k4];
        #pragma unroll
        for (int kk=0;kk<4;kk++){
            float hk = (kk==0)?h.x:(kk==1)?h.y:(kk==2)?h.z:h.w;
            const float4* Wr=(const float4*)(sm+G_F2 + (k4*4+kk)*32);
            #pragma unroll
            for (int j4=0;j4<8;j4++){
                float4 w=Wr[j4];
                z2[4*j4]  =fmaf(hk,w.x,z2[4*j4]);
                z2[4*j4+1]=fmaf(hk,w.y,z2[4*j4+1]);
                z2[4*j4+2]=fmaf(hk,w.z,z2[4*j4+2]);
                z2[4*j4+3]=fmaf(hk,w.w,z2[4*j4+3]);
            }
        }
    }
    float o[NCLS];
    #pragma unroll
    for (int c=0;c<NCLS;c++) o[c]=sm[G_FB3+c];
    #pragma unroll
    for (int k=0;k<32;k++){
        float hk = fmaxf(z2[k],0.f);
        #pragma unroll
        for (int c=0;c<NCLS;c++) o[c]=fmaf(hk, sm[G_F3 + k*NCLS + c], o[c]);
    }
    #pragma unroll
    for (int c=0;c<NCLS;c++) out[row*NCLS + c] = o[c];
}

// ---------------- launch ----------------
extern "C" void kernel_launch(void* const* d_in, const int* in_sizes, int n_in,
                              void* d_out, int out_size)
{
    const float* x     = (const float*)d_in[0];
    const int*   batch = (const int*)d_in[1];
    int n = in_sizes[0];

    cudaFuncSetAttribute(node_kernel,  cudaFuncAttributeMaxDynamicSharedMemorySize, NODE_SMEM_BYTES);
    cudaFuncSetAttribute(graph_kernel, cudaFuncAttributeMaxDynamicSharedMemorySize, GRAPH_SMEM_BYTES);

    prep_kernel<<<1,256>>>(
        (const float*)d_in[3],  (const float*)d_in[4],  (const float*)d_in[5],
        (const float*)d_in[6],  (const float*)d_in[7],  (const float*)d_in[8],
        (const float*)d_in[9],  (const float*)d_in[10],
        (const float*)d_in[11], (const float*)d_in[12], (const float*)d_in[13],
        (const float*)d_in[14], (const float*)d_in[15],
        (const float*)d_in[16], (const float*)d_in[17], (const float*)d_in[18],
        (const float*)d_in[19], (const float*)d_in[20], (const float*)d_in[21],
        (const float*)d_in[22], (const float*)d_in[23], (const float*)d_in[24],
        (const float*)d_in[25], (const float*)d_in[26]);

    zero_kernel<<<(BGR*128 + 255)/256, 256>>>();
    node_kernel<<<(n + 255)/256, 256, NODE_SMEM_BYTES>>>(x, batch, n);
    graph_kernel<<<BGR/256, 256, GRAPH_SMEM_BYTES>>>((float*)d_out);
}